// round 15
// baseline (speedup 1.0000x reference)
#include <cuda_runtime.h>
#include <cuda_fp16.h>
#include <cstdint>

typedef unsigned long long ull;

#define Bb   2
#define Nn   512
#define Hh   1024
#define HDd  512
#define Mm   1024          // B*N rows
#define NTOT 1536          // fused GEMM output columns

// GEMM tiling
#define BM 128
#define BN 64
#define BK 64
#define KT (Hh / BK)             // 16 k-tiles
#define STG 24576                // A(16KB)+B(8KB) per stage
#define NSTG 4
#define EP_PITCH 66              // epilogue smem pitch (floats)
#define GEMM_SMEM (NSTG * STG)   // 98304

// end kernel smem (floats): W dup 1024 | per group g (4): A 2x2048 + C 2x1024 (=6144)
#define END_SMEM ((1024 + 4 * 6144) * 4)   // 102400 bytes
#define END_CTAS 148
#define NUNITS 4096                         // 128 tiles x 32 chunks

// -------- scratch --------
__device__ __half g_Ah[Mm * Hh];            // emb in fp16
__device__ __half g_Bh[NTOT * Hh];          // weights transposed [n][k], fp16
__device__ float  g_aD[HDd * 2 * Mm];       // (emb@W1_start + b_e1)^T duplicated: [d][2m]=(v,v)
__device__ float  g_cT[HDd * Mm];           // (emb@W1_end)^T  [d][m]

// -------- PTX helpers --------
__device__ __forceinline__ uint32_t smem_u32(const void* p) {
    uint32_t a;
    asm("{ .reg .u64 t; cvta.to.shared.u64 t, %1; cvt.u32.u64 %0, t; }" : "=r"(a) : "l"(p));
    return a;
}
#define CP16(dst, src) \
    asm volatile("cp.async.cg.shared.global [%0], [%1], 16;" :: "r"(dst), "l"(src) : "memory")
#define CP_COMMIT() asm volatile("cp.async.commit_group;" ::: "memory")

#define LDSM4(r0, r1, r2, r3, a) \
    asm volatile("ldmatrix.sync.aligned.m8n8.x4.shared.b16 {%0,%1,%2,%3}, [%4];" \
        : "=r"(r0), "=r"(r1), "=r"(r2), "=r"(r3) : "r"(a))

#define MMA16816(d, a0, a1, a2, a3, b0, b1) \
    asm volatile("mma.sync.aligned.m16n8k16.row.col.f32.f16.f16.f32 " \
        "{%0,%1,%2,%3}, {%4,%5,%6,%7}, {%8,%9}, {%0,%1,%2,%3};" \
        : "+f"((d)[0]), "+f"((d)[1]), "+f"((d)[2]), "+f"((d)[3]) \
        : "r"(a0), "r"(a1), "r"(a2), "r"(a3), "r"(b0), "r"(b1))

// -------- weight gather (fused [W_s1 | W_e1a | W_e1b] indexed [k][n]) --------
__device__ __forceinline__ float loadW(const float* __restrict__ W_s1,
                                       const float* __restrict__ W_e1,
                                       int k, int n) {
    if (n < 512)       return W_s1[(size_t)k * 512 + n];
    else if (n < 1024) return W_e1[(size_t)k * 512 + (n - 512)];
    else               return W_e1[(size_t)(1024 + k) * 512 + (n - 1024)];
}

// -------- merged prepass (MLP-heavy) + output init (b_s2 / b_e2) --------
__global__ __launch_bounds__(256) void prep_kernel(const float* __restrict__ emb,
                                                   const float* __restrict__ W_s1,
                                                   const float* __restrict__ W_e1,
                                                   const float* __restrict__ b_s2,
                                                   const float* __restrict__ b_e2,
                                                   float* __restrict__ out) {
    __shared__ float sm[2][32][33];
    const int bx = blockIdx.x, t = threadIdx.x;
    if (bx < 256) {
        const int base = bx * 256 + t;
        float4 v[4];
#pragma unroll
        for (int rep = 0; rep < 4; rep++)
            v[rep] = ((const float4*)emb)[base + rep * 65536];
        __half2* A = (__half2*)g_Ah;
#pragma unroll
        for (int rep = 0; rep < 4; rep++) {
            int i = base + rep * 65536;
            A[2 * i]     = __floats2half2_rn(v[rep].x, v[rep].y);
            A[2 * i + 1] = __floats2half2_rn(v[rep].z, v[rep].w);
        }
        if (bx < 4) out[bx * 256 + t] = b_s2[0];
        // init end-logits region with b_e2 (atomicAdd partials land on top)
        const float be = b_e2[0];
        const float4 be4 = make_float4(be, be, be, be);
        float4* oe = (float4*)(out + Mm);
        oe[base * 2]     = be4;
        oe[base * 2 + 1] = be4;
    } else {
        const int wb = bx - 256;                       // 0..767 -> tiles 2wb, 2wb+1
        const int c = t & 31, r = t >> 5;
        const int tt0 = wb * 2, tt1 = tt0 + 1;
        const int n00 = (tt0 % 48) * 32, k00 = (tt0 / 48) * 32;
        const int n01 = (tt1 % 48) * 32, k01 = (tt1 / 48) * 32;
        float v0[4], v1[4];
#pragma unroll
        for (int p = 0; p < 4; p++) v0[p] = loadW(W_s1, W_e1, k00 + r + 8 * p, n00 + c);
#pragma unroll
        for (int p = 0; p < 4; p++) v1[p] = loadW(W_s1, W_e1, k01 + r + 8 * p, n01 + c);
#pragma unroll
        for (int p = 0; p < 4; p++) { sm[0][r + 8 * p][c] = v0[p]; sm[1][r + 8 * p][c] = v1[p]; }
        __syncthreads();
#pragma unroll
        for (int p = 0; p < 4; p++) {
            int ln = r + 8 * p, lk = c;
            g_Bh[(size_t)(n00 + ln) * Hh + k00 + lk] = __float2half_rn(sm[0][lk][ln]);
            g_Bh[(size_t)(n01 + ln) * Hh + k01 + lk] = __float2half_rn(sm[1][lk][ln]);
        }
    }
}

// -------- HMMA GEMM: C[1024,1536] = emb_fp16 @ [W_s1|W_e1a|W_e1b]_fp16 --------
__device__ __forceinline__ void load_stage(uint32_t abase, const __half* __restrict__ A,
                                           const __half* __restrict__ B, int kt, int tid) {
    const uint32_t bbase = abase + 16384;
#pragma unroll
    for (int i = 0; i < 4; i++) {
        int c = tid + i * 256;             // 1024 16B chunks for A (128 rows x 8)
        int row = c >> 3, kc = c & 7;
        uint32_t dst = abase + (uint32_t)(row * 128) + (uint32_t)((kc ^ (row & 7)) << 4);
        CP16(dst, A + (size_t)row * Hh + kt * BK + kc * 8);
    }
#pragma unroll
    for (int i = 0; i < 2; i++) {
        int c = tid + i * 256;             // 512 chunks for B (64 rows x 8)
        int row = c >> 3, kc = c & 7;
        uint32_t dst = bbase + (uint32_t)(row * 128) + (uint32_t)((kc ^ (row & 7)) << 4);
        CP16(dst, B + (size_t)row * Hh + kt * BK + kc * 8);
    }
}

__global__ __launch_bounds__(256, 2) void gemm_kernel(
    const float* __restrict__ b_s1, const float* __restrict__ w_s2,
    const float* __restrict__ b_e1, float* __restrict__ out)
{
    extern __shared__ char smem[];
    const uint32_t sb = smem_u32(smem);

    const int tid = threadIdx.x, lane = tid & 31, wid = tid >> 5;
    const int wm = wid & 3;                 // warp row group (32 rows)
    const int wn = wid >> 2;                // warp col group (32 cols)
    const int m0 = blockIdx.y * BM;
    const int n0 = blockIdx.x * BN;
    const __half* Ap = g_Ah + (size_t)m0 * Hh;
    const __half* Bp = g_Bh + (size_t)n0 * Hh;

    float acc[2][4][4];
#pragma unroll
    for (int i = 0; i < 2; i++)
#pragma unroll
        for (int j = 0; j < 4; j++)
#pragma unroll
            for (int r = 0; r < 4; r++) acc[i][j][r] = 0.f;

    const int a_row = wm * 32 + (lane & 15);
    const int b_rowb = wn * 32 + (lane & 15);
    const int l_kc  = lane >> 4;

    // 4-stage prologue: 3 stages in flight
    load_stage(sb,           Ap, Bp, 0, tid); CP_COMMIT();
    load_stage(sb + STG,     Ap, Bp, 1, tid); CP_COMMIT();
    load_stage(sb + 2 * STG, Ap, Bp, 2, tid); CP_COMMIT();

    for (int t = 0; t < KT; t++) {
        if (t <= KT - 3)      asm volatile("cp.async.wait_group 2;" ::: "memory");
        else if (t == KT - 2) asm volatile("cp.async.wait_group 1;" ::: "memory");
        else                  asm volatile("cp.async.wait_group 0;" ::: "memory");
        __syncthreads();

        if (t + 3 < KT) {
            load_stage(sb + (uint32_t)(((t + 3) & 3) * STG), Ap, Bp, t + 3, tid);
            CP_COMMIT();
        }

        const uint32_t Ab = sb + (uint32_t)((t & 3) * STG);
        const uint32_t Bbs = Ab + 16384;
#pragma unroll
        for (int ks = 0; ks < 4; ks++) {              // 4 k16-steps in BK=64
            const int kc = 2 * ks + l_kc;
            uint32_t a0r[4], a1r[4];
            {
                int r = a_row;
                LDSM4(a0r[0], a0r[1], a0r[2], a0r[3],
                      Ab + (uint32_t)(r * 128) + (uint32_t)((kc ^ (r & 7)) << 4));
                r = a_row + 16;
                LDSM4(a1r[0], a1r[1], a1r[2], a1r[3],
                      Ab + (uint32_t)(r * 128) + (uint32_t)((kc ^ (r & 7)) << 4));
            }
#pragma unroll
            for (int jg = 0; jg < 2; jg++) {          // 2 n16-groups = 4 n8-tiles
                int r = b_rowb + 16 * jg;
                uint32_t b0, b1, b2, b3;
                LDSM4(b0, b1, b2, b3,
                      Bbs + (uint32_t)(r * 128) + (uint32_t)((kc ^ (r & 7)) << 4));
                MMA16816(acc[0][2 * jg],     a0r[0], a0r[1], a0r[2], a0r[3], b0, b2);
                MMA16816(acc[0][2 * jg + 1], a0r[0], a0r[1], a0r[2], a0r[3], b1, b3);
                MMA16816(acc[1][2 * jg],     a1r[0], a1r[1], a1r[2], a1r[3], b0, b2);
                MMA16816(acc[1][2 * jg + 1], a1r[0], a1r[1], a1r[2], a1r[3], b1, b3);
            }
        }
    }
    __syncthreads();

    // ---- dump accumulators to smem [BM][EP_PITCH] ----
    float* eps = (float*)smem;
    const int rbase = wm * 32 + (lane >> 2);
    const int cbase = wn * 32 + (lane & 3) * 2;
#pragma unroll
    for (int i = 0; i < 2; i++)
#pragma unroll
        for (int j = 0; j < 4; j++) {
            int rr = rbase + i * 16;
            int cc = cbase + j * 8;
            *(float2*)&eps[rr * EP_PITCH + cc]       = make_float2(acc[i][j][0], acc[i][j][1]);
            *(float2*)&eps[(rr + 8) * EP_PITCH + cc] = make_float2(acc[i][j][2], acc[i][j][3]);
        }
    __syncthreads();

    // ---- epilogue ----
    const int blk = n0 >> 9;                 // 0 / 1 / 2
    const int cb  = n0 & 511;
    if (blk == 0) {
        const int r = tid >> 1, h = tid & 1;
        float s = 0.f;
#pragma unroll 8
        for (int c = 0; c < 32; c++) {
            int d = cb + h * 32 + c;
            s += fmaxf(eps[r * EP_PITCH + h * 32 + c] + __ldg(b_s1 + d), 0.f) * __ldg(w_s2 + d);
        }
        s += __shfl_xor_sync(0xffffffffu, s, 1);
        if (h == 0) atomicAdd(out + m0 + r, s);
    } else if (blk == 1) {
#pragma unroll 4
        for (int it = 0; it < 32; it++) {
            int idx = it * 256 + tid;            // 8192 = 128m x 64d
            int m = idx & 127, dl = idx >> 7;
            int d = cb + dl;
            float v = eps[m * EP_PITCH + dl] + __ldg(b_e1 + d);
            *(float2*)(g_aD + (size_t)d * (2 * Mm) + 2 * (m0 + m)) = make_float2(v, v);
        }
    } else {
#pragma unroll 4
        for (int it = 0; it < 32; it++) {
            int idx = it * 256 + tid;
            int m = idx & 127, dl = idx >> 7;
            g_cT[(size_t)(cb + dl) * Mm + m0 + m] = eps[m * EP_PITCH + dl];
        }
    }
}

// -------- end logits: snake-balanced over 148 CTAs, packed f32x2, 4 groups --------
#define RELUFMA(acc, a2, c2, w2) \
    asm("{\n\t.reg .f32 lo, hi; .reg .b64 s, m;\n\t" \
        "add.rn.f32x2 s, %1, %2;\n\t" \
        "mov.b64 {lo, hi}, s;\n\t" \
        "max.f32 lo, lo, 0f00000000;\n\t" \
        "max.f32 hi, hi, 0f00000000;\n\t" \
        "mov.b64 m, {lo, hi};\n\t" \
        "fma.rn.f32x2 %0, m, %3, %0;\n\t}" \
        : "+l"(acc) : "l"(a2), "l"(c2), "l"(w2))

#define ADD2(acc, o) asm("add.rn.f32x2 %0, %0, %1;" : "+l"(acc) : "l"(o))
#define HBAR(id) asm volatile("bar.sync %0, 128;" :: "r"(id) : "memory")

__global__ __launch_bounds__(512) void end_kernel(
    const float* __restrict__ w_e2, float* __restrict__ out_end)
{
    extern __shared__ float sf[];
    // floats: [0,1024) W dup | group g at 1024 + g*6144: A 2x2048 then C 2x1024
    float2* Wsm = (float2*)sf;
    const uint32_t sb = smem_u32(sf);

    const int t  = threadIdx.x;
    const int gq = t >> 7;          // group id 0..3
    const int lt = t & 127;         // lane within group
    const int bid = blockIdx.x;

    { float w = w_e2[t]; Wsm[t] = make_float2(w, w); }   // all 512 d

    const int tx = lt & 15;          // j-group: 4 j at tx*4
    const int ty = lt >> 4;          // i-group: 8 i at ty*8

    const uint32_t GB  = (uint32_t)(1024 + gq * 6144) * 4;
    const float*   GBf = sf + 1024 + gq * 6144;

    // unit range for this CTA (static snake partition of 4096 units)
    const int u0 = (int)(((long long)bid * NUNITS) / END_CTAS);
    const int u1 = (int)(((long long)(bid + 1) * NUNITS) / END_CTAS);

    ull acc[8][2];
#pragma unroll
    for (int a = 0; a < 8; a++) { acc[a][0] = 0; acc[a][1] = 0; }

    __syncthreads();                 // W visible to all groups

#define LOAD_CHUNK(ch, st) do { \
    const uint32_t _Ab = sb + GB + (uint32_t)((st) * 2048 * 4); \
    const uint32_t _Cb = sb + GB + (uint32_t)((4096 + (st) * 1024) * 4); \
    const float* _As = Asrc0 + (size_t)((ch) * 16) * 2048; \
    const float* _Cs = Csrc0 + (size_t)((ch) * 16) * 1024; \
    _Pragma("unroll") \
    for (int _i = 0; _i < 4; _i++) { \
        int _c = lt + _i * 128; \
        int _r = _c >> 5, _q = _c & 31; \
        CP16(_Ab + (uint32_t)(_r * 512 + _q * 16), _As + (size_t)_r * 2048 + _q * 4); \
    } \
    _Pragma("unroll") \
    for (int _i = 0; _i < 2; _i++) { \
        int _c = lt + _i * 128; \
        int _r = _c >> 4, _q = _c & 15; \
        CP16(_Cb + (uint32_t)(_r * 256 + _q * 16), _Cs + (size_t)_r * 1024 + _q * 4); \
    } \
} while (0)

    int useg = u0;
    while (useg < u1) {
        const int tile = useg >> 5;
        const int segEnd = min(u1, (tile + 1) * 32);
        const int L = segEnd - useg;            // chunks in this segment (1..32)
        const int cb0 = useg & 31;              // first chunk within tile
        const int bz = tile >> 6, iy = (tile >> 3) & 7, jx = tile & 7;
        const int i0 = iy * 64, j0 = jx * 64;
        const int mi = bz * Nn + i0, mj = bz * Nn + j0;
        const float* Asrc0 = g_aD + 2 * mi;
        const float* Csrc0 = g_cT + mj;

        int l = gq, st = 0;
        if (l < L) { LOAD_CHUNK(cb0 + l, 0); }
        CP_COMMIT();
        while (l < L) {
            const int ln = l + 4;
            if (ln < L) {
                LOAD_CHUNK(cb0 + ln, st ^ 1);
                CP_COMMIT();
                asm volatile("cp.async.wait_group 1;" ::: "memory");
            } else {
                asm volatile("cp.async.wait_group 0;" ::: "memory");
            }
            HBAR(1 + gq);

            const float* Abuf = GBf + st * 2048;
            const float* Cbuf = GBf + 4096 + st * 1024;
            const int wb = (cb0 + l) * 16;
#pragma unroll 8
            for (int dc = 0; dc < 16; dc++) {
                ull w2 = *(const ull*)&Wsm[wb + dc];
                const float* ar = Abuf + dc * 128 + ty * 16;
                ulonglong2 aP0 = *(const ulonglong2*)ar;
                ulonglong2 aP1 = *(const ulonglong2*)(ar + 4);
                ulonglong2 aP2 = *(const ulonglong2*)(ar + 8);
                ulonglong2 aP3 = *(const ulonglong2*)(ar + 12);
                ulonglong2 cP  = *(const ulonglong2*)(Cbuf + dc * 64 + tx * 4);
                RELUFMA(acc[0][0], aP0.x, cP.x, w2); RELUFMA(acc[0][1], aP0.x, cP.y, w2);
                RELUFMA(acc[1][0], aP0.y, cP.x, w2); RELUFMA(acc[1][1], aP0.y, cP.y, w2);
                RELUFMA(acc[2][0], aP1.x, cP.x, w2); RELUFMA(acc[2][1], aP1.x, cP.y, w2);
                RELUFMA(acc[3][0], aP1.y, cP.x, w2); RELUFMA(acc[3][1], aP1.y, cP.y, w2);
                RELUFMA(acc[4][0], aP2.x, cP.x, w2); RELUFMA(acc[4][1], aP2.x, cP.y, w2);
                RELUFMA(acc[5][0], aP2.y, cP.x, w2); RELUFMA(acc[5][1], aP2.y, cP.y, w2);
                RELUFMA(acc[6][0], aP3.x, cP.x, w2); RELUFMA(acc[6][1], aP3.x, cP.y, w2);
                RELUFMA(acc[7][0], aP3.y, cP.x, w2); RELUFMA(acc[7][1], aP3.y, cP.y, w2);
            }
            HBAR(1 + gq);
            l = ln; st ^= 1;
        }

        // ---- combine groups and flush this tile's partial via atomicAdd ----
        __syncthreads();
        if (gq != 0) {
            ull* dmp = (ull*)GBf;               // reuse this group's A region (16KB)
#pragma unroll
            for (int i = 0; i < 8; i++) {
                dmp[(2 * i) * 128 + lt]     = acc[i][0];
                dmp[(2 * i + 1) * 128 + lt] = acc[i][1];
            }
        }
        __syncthreads();
        if (gq == 0) {
#pragma unroll
            for (int i = 0; i < 8; i++) {
#pragma unroll
                for (int gg = 1; gg < 4; gg++) {
                    const ull* dmp = (const ull*)(sf + 1024 + gg * 6144);
                    ADD2(acc[i][0], dmp[(2 * i) * 128 + lt]);
                    ADD2(acc[i][1], dmp[(2 * i + 1) * 128 + lt]);
                }
                float l0, h0, l1, h1;
                asm("mov.b64 {%0, %1}, %2;" : "=f"(l0), "=f"(h0) : "l"(acc[i][0]));
                asm("mov.b64 {%0, %1}, %2;" : "=f"(l1), "=f"(h1) : "l"(acc[i][1]));
                size_t r0 = (size_t)(bz * Nn + i0 + ty * 8 + i) * Nn + j0 + tx * 4;
                atomicAdd(out_end + r0 + 0, l0);
                atomicAdd(out_end + r0 + 1, h0);
                atomicAdd(out_end + r0 + 2, l1);
                atomicAdd(out_end + r0 + 3, h1);
            }
        }
        __syncthreads();                        // dumps read before A-region reuse
#pragma unroll
        for (int a = 0; a < 8; a++) { acc[a][0] = 0; acc[a][1] = 0; }
        useg = segEnd;
    }
}

// -------- host --------
extern "C" void kernel_launch(void* const* d_in, const int* in_sizes, int n_in,
                              void* d_out, int out_size)
{
    (void)in_sizes; (void)n_in; (void)out_size;
    const float* emb  = (const float*)d_in[0];
    const float* W_s1 = (const float*)d_in[1];
    const float* b_s1 = (const float*)d_in[2];
    const float* w_s2 = (const float*)d_in[3];
    const float* b_s2 = (const float*)d_in[4];
    const float* W_e1 = (const float*)d_in[5];
    const float* b_e1 = (const float*)d_in[6];
    const float* w_e2 = (const float*)d_in[7];
    const float* b_e2 = (const float*)d_in[8];
    float* out = (float*)d_out;

    static bool attr_done = false;
    if (!attr_done) {
        cudaFuncSetAttribute(gemm_kernel, cudaFuncAttributeMaxDynamicSharedMemorySize, GEMM_SMEM);
        cudaFuncSetAttribute(end_kernel, cudaFuncAttributeMaxDynamicSharedMemorySize, END_SMEM);
        attr_done = true;
    }

    prep_kernel<<<1024, 256>>>(emb, W_s1, W_e1, b_s2, b_e2, out);

    dim3 gg(NTOT / BN, Mm / BM);                  // 24 x 8 = 192 CTAs
    gemm_kernel<<<gg, 256, GEMM_SMEM>>>(b_s1, w_s2, b_e1, out);

    end_kernel<<<END_CTAS, 512, END_SMEM>>>(w_e2, out + Mm);
}

// round 16
// speedup vs baseline: 1.1225x; 1.1225x over previous
#include <cuda_runtime.h>
#include <cuda_fp16.h>
#include <cstdint>

typedef unsigned long long ull;

#define Bb   2
#define Nn   512
#define Hh   1024
#define HDd  512
#define Mm   1024          // B*N rows
#define NTOT 1536          // fused GEMM output columns

// GEMM tiling
#define BM 128
#define BN 64
#define BK 64
#define KT (Hh / BK)             // 16 k-tiles
#define STG 24576                // A(16KB)+B(8KB) per stage
#define NSTG 4
#define EP_PITCH 66              // epilogue smem pitch (floats)
#define GEMM_SMEM (NSTG * STG)   // 98304

// end kernel smem (bytes): W fp16 1KB | A 2x4096 | C 2x8192 | D 32x68 f32
#define E_W 0
#define E_A 1024
#define E_C 9216
#define E_D 25600
#define END_SMEM 34304

// -------- scratch --------
__device__ __half g_Ah[Mm * Hh];            // emb in fp16
__device__ __half g_Bh[NTOT * Hh];          // weights transposed [n][k], fp16
__device__ __half g_aH[Mm * HDd];           // (emb@W1_start + b_e1) fp16 [m][d]
__device__ __half g_cH[Mm * HDd];           // (emb@W1_end)          fp16 [m][d]

// -------- PTX helpers --------
__device__ __forceinline__ uint32_t smem_u32(const void* p) {
    uint32_t a;
    asm("{ .reg .u64 t; cvta.to.shared.u64 t, %1; cvt.u32.u64 %0, t; }" : "=r"(a) : "l"(p));
    return a;
}
#define CP16(dst, src) \
    asm volatile("cp.async.cg.shared.global [%0], [%1], 16;" :: "r"(dst), "l"(src) : "memory")
#define CP_COMMIT() asm volatile("cp.async.commit_group;" ::: "memory")

#define LDSM4(r0, r1, r2, r3, a) \
    asm volatile("ldmatrix.sync.aligned.m8n8.x4.shared.b16 {%0,%1,%2,%3}, [%4];" \
        : "=r"(r0), "=r"(r1), "=r"(r2), "=r"(r3) : "r"(a))

#define MMA16816(d, a0, a1, a2, a3, b0, b1) \
    asm volatile("mma.sync.aligned.m16n8k16.row.col.f32.f16.f16.f32 " \
        "{%0,%1,%2,%3}, {%4,%5,%6,%7}, {%8,%9}, {%0,%1,%2,%3};" \
        : "+f"((d)[0]), "+f"((d)[1]), "+f"((d)[2]), "+f"((d)[3]) \
        : "r"(a0), "r"(a1), "r"(a2), "r"(a3), "r"(b0), "r"(b1))

#define LDS32(r, a) asm("ld.shared.b32 %0, [%1];" : "=r"(r) : "r"(a))

// relu(x+y) in packed fp16
#define PRELU(p, x, y) \
    asm("{\n\t.reg .b32 s;\n\t" \
        "add.f16x2 s, %1, %2;\n\t" \
        "max.f16x2 %0, s, %3;\n\t}" \
        : "=r"(p) : "r"(x), "r"(y), "r"(0u))

// -------- weight gather (fused [W_s1 | W_e1a | W_e1b] indexed [k][n]) --------
__device__ __forceinline__ float loadW(const float* __restrict__ W_s1,
                                       const float* __restrict__ W_e1,
                                       int k, int n) {
    if (n < 512)       return W_s1[(size_t)k * 512 + n];
    else if (n < 1024) return W_e1[(size_t)k * 512 + (n - 512)];
    else               return W_e1[(size_t)(1024 + k) * 512 + (n - 1024)];
}

// -------- merged prepass (MLP-heavy) --------
__global__ __launch_bounds__(256) void prep_kernel(const float* __restrict__ emb,
                                                   const float* __restrict__ W_s1,
                                                   const float* __restrict__ W_e1,
                                                   const float* __restrict__ b_s2,
                                                   float* __restrict__ out) {
    __shared__ float sm[2][32][33];
    const int bx = blockIdx.x, t = threadIdx.x;
    if (bx < 256) {
        const int base = bx * 256 + t;
        float4 v[4];
#pragma unroll
        for (int rep = 0; rep < 4; rep++)
            v[rep] = ((const float4*)emb)[base + rep * 65536];
        __half2* A = (__half2*)g_Ah;
#pragma unroll
        for (int rep = 0; rep < 4; rep++) {
            int i = base + rep * 65536;
            A[2 * i]     = __floats2half2_rn(v[rep].x, v[rep].y);
            A[2 * i + 1] = __floats2half2_rn(v[rep].z, v[rep].w);
        }
        if (bx < 4) out[bx * 256 + t] = b_s2[0];
    } else {
        const int wb = bx - 256;                       // 0..767 -> tiles 2wb, 2wb+1
        const int c = t & 31, r = t >> 5;
        const int tt0 = wb * 2, tt1 = tt0 + 1;
        const int n00 = (tt0 % 48) * 32, k00 = (tt0 / 48) * 32;
        const int n01 = (tt1 % 48) * 32, k01 = (tt1 / 48) * 32;
        float v0[4], v1[4];
#pragma unroll
        for (int p = 0; p < 4; p++) v0[p] = loadW(W_s1, W_e1, k00 + r + 8 * p, n00 + c);
#pragma unroll
        for (int p = 0; p < 4; p++) v1[p] = loadW(W_s1, W_e1, k01 + r + 8 * p, n01 + c);
#pragma unroll
        for (int p = 0; p < 4; p++) { sm[0][r + 8 * p][c] = v0[p]; sm[1][r + 8 * p][c] = v1[p]; }
        __syncthreads();
#pragma unroll
        for (int p = 0; p < 4; p++) {
            int ln = r + 8 * p, lk = c;
            g_Bh[(size_t)(n00 + ln) * Hh + k00 + lk] = __float2half_rn(sm[0][lk][ln]);
            g_Bh[(size_t)(n01 + ln) * Hh + k01 + lk] = __float2half_rn(sm[1][lk][ln]);
        }
    }
}

// -------- HMMA GEMM: C[1024,1536] = emb_fp16 @ [W_s1|W_e1a|W_e1b]_fp16 --------
__device__ __forceinline__ void load_stage(uint32_t abase, const __half* __restrict__ A,
                                           const __half* __restrict__ B, int kt, int tid) {
    const uint32_t bbase = abase + 16384;
#pragma unroll
    for (int i = 0; i < 4; i++) {
        int c = tid + i * 256;             // 1024 16B chunks for A (128 rows x 8)
        int row = c >> 3, kc = c & 7;
        uint32_t dst = abase + (uint32_t)(row * 128) + (uint32_t)((kc ^ (row & 7)) << 4);
        CP16(dst, A + (size_t)row * Hh + kt * BK + kc * 8);
    }
#pragma unroll
    for (int i = 0; i < 2; i++) {
        int c = tid + i * 256;             // 512 chunks for B (64 rows x 8)
        int row = c >> 3, kc = c & 7;
        uint32_t dst = bbase + (uint32_t)(row * 128) + (uint32_t)((kc ^ (row & 7)) << 4);
        CP16(dst, B + (size_t)row * Hh + kt * BK + kc * 8);
    }
}

__global__ __launch_bounds__(256, 2) void gemm_kernel(
    const float* __restrict__ b_s1, const float* __restrict__ w_s2,
    const float* __restrict__ b_e1, float* __restrict__ out)
{
    extern __shared__ char smem[];
    const uint32_t sb = smem_u32(smem);

    const int tid = threadIdx.x, lane = tid & 31, wid = tid >> 5;
    const int wm = wid & 3;                 // warp row group (32 rows)
    const int wn = wid >> 2;                // warp col group (32 cols)
    const int m0 = blockIdx.y * BM;
    const int n0 = blockIdx.x * BN;
    const __half* Ap = g_Ah + (size_t)m0 * Hh;
    const __half* Bp = g_Bh + (size_t)n0 * Hh;

    float acc[2][4][4];
#pragma unroll
    for (int i = 0; i < 2; i++)
#pragma unroll
        for (int j = 0; j < 4; j++)
#pragma unroll
            for (int r = 0; r < 4; r++) acc[i][j][r] = 0.f;

    const int a_row = wm * 32 + (lane & 15);
    const int b_rowb = wn * 32 + (lane & 15);
    const int l_kc  = lane >> 4;

    // 4-stage prologue: 3 stages in flight
    load_stage(sb,           Ap, Bp, 0, tid); CP_COMMIT();
    load_stage(sb + STG,     Ap, Bp, 1, tid); CP_COMMIT();
    load_stage(sb + 2 * STG, Ap, Bp, 2, tid); CP_COMMIT();

    for (int t = 0; t < KT; t++) {
        if (t <= KT - 3)      asm volatile("cp.async.wait_group 2;" ::: "memory");
        else if (t == KT - 2) asm volatile("cp.async.wait_group 1;" ::: "memory");
        else                  asm volatile("cp.async.wait_group 0;" ::: "memory");
        __syncthreads();

        if (t + 3 < KT) {
            load_stage(sb + (uint32_t)(((t + 3) & 3) * STG), Ap, Bp, t + 3, tid);
            CP_COMMIT();
        }

        const uint32_t Ab = sb + (uint32_t)((t & 3) * STG);
        const uint32_t Bbs = Ab + 16384;
#pragma unroll
        for (int ks = 0; ks < 4; ks++) {              // 4 k16-steps in BK=64
            const int kc = 2 * ks + l_kc;
            uint32_t a0r[4], a1r[4];
            {
                int r = a_row;
                LDSM4(a0r[0], a0r[1], a0r[2], a0r[3],
                      Ab + (uint32_t)(r * 128) + (uint32_t)((kc ^ (r & 7)) << 4));
                r = a_row + 16;
                LDSM4(a1r[0], a1r[1], a1r[2], a1r[3],
                      Ab + (uint32_t)(r * 128) + (uint32_t)((kc ^ (r & 7)) << 4));
            }
#pragma unroll
            for (int jg = 0; jg < 2; jg++) {          // 2 n16-groups = 4 n8-tiles
                int r = b_rowb + 16 * jg;
                uint32_t b0, b1, b2, b3;
                LDSM4(b0, b1, b2, b3,
                      Bbs + (uint32_t)(r * 128) + (uint32_t)((kc ^ (r & 7)) << 4));
                MMA16816(acc[0][2 * jg],     a0r[0], a0r[1], a0r[2], a0r[3], b0, b2);
                MMA16816(acc[0][2 * jg + 1], a0r[0], a0r[1], a0r[2], a0r[3], b1, b3);
                MMA16816(acc[1][2 * jg],     a1r[0], a1r[1], a1r[2], a1r[3], b0, b2);
                MMA16816(acc[1][2 * jg + 1], a1r[0], a1r[1], a1r[2], a1r[3], b1, b3);
            }
        }
    }
    __syncthreads();

    // ---- dump accumulators to smem [BM][EP_PITCH] ----
    float* eps = (float*)smem;
    const int rbase = wm * 32 + (lane >> 2);
    const int cbase = wn * 32 + (lane & 3) * 2;
#pragma unroll
    for (int i = 0; i < 2; i++)
#pragma unroll
        for (int j = 0; j < 4; j++) {
            int rr = rbase + i * 16;
            int cc = cbase + j * 8;
            *(float2*)&eps[rr * EP_PITCH + cc]       = make_float2(acc[i][j][0], acc[i][j][1]);
            *(float2*)&eps[(rr + 8) * EP_PITCH + cc] = make_float2(acc[i][j][2], acc[i][j][3]);
        }
    __syncthreads();

    // ---- epilogue ----
    const int blk = n0 >> 9;                 // 0 / 1 / 2
    const int cb  = n0 & 511;
    if (blk == 0) {
        const int r = tid >> 1, h = tid & 1;
        float s = 0.f;
#pragma unroll 8
        for (int c = 0; c < 32; c++) {
            int d = cb + h * 32 + c;
            s += fmaxf(eps[r * EP_PITCH + h * 32 + c] + __ldg(b_s1 + d), 0.f) * __ldg(w_s2 + d);
        }
        s += __shfl_xor_sync(0xffffffffu, s, 1);
        if (h == 0) atomicAdd(out + m0 + r, s);
    } else if (blk == 1) {
#pragma unroll 4
        for (int it = 0; it < 32; it++) {
            int idx = it * 256 + tid;            // 8192 = 128m x 64d
            int dl = idx & 63, m = idx >> 6;
            int d = cb + dl;
            g_aH[(size_t)(m0 + m) * HDd + d] =
                __float2half_rn(eps[m * EP_PITCH + dl] + __ldg(b_e1 + d));
        }
    } else {
#pragma unroll 4
        for (int it = 0; it < 32; it++) {
            int idx = it * 256 + tid;
            int dl = idx & 63, m = idx >> 6;
            g_cH[(size_t)(m0 + m) * HDd + cb + dl] =
                __float2half_rn(eps[m * EP_PITCH + dl]);
        }
    }
}

// ===========================================================================
// end logits v3: fp16 packed relu + HMMA, 32i x 64j tiles (grid 256, 2 CTA/SM),
// i-unrolled x2 (two independent D accumulator chains per warp).
// Warps: 4 j16-blocks x 2 i-halves (16 i each). Per d-chunk(64): c/w frags in
// regs; per i-pair: build P frags (add.f16x2+max.f16x2), 4 MMAs per i into
// separate D sets; col0 accumulated into smem D[32][68] (warp-disjoint).
// ===========================================================================
__global__ __launch_bounds__(256) void end2_kernel(
    const float* __restrict__ w_e2, const float* __restrict__ b_e2,
    float* __restrict__ out_end)
{
    extern __shared__ char smc[];
    const uint32_t sb = smem_u32(smc);
    float* Dsm = (float*)(smc + E_D);

    const int tid = threadIdx.x, l = tid & 31, w = tid >> 5;
    const int g = l >> 2, t = l & 3;
    const int jb = (w & 3) * 16;
    const int i0w = (w >> 2) * 16;
    const int bz = blockIdx.z, i0 = blockIdx.y * 32, j0 = blockIdx.x * 64;
    const int mi = bz * Nn + i0, mj = bz * Nn + j0;

    // W fp32 -> fp16 into smem (512 halfs)
    {
        float2 v = ((const float2*)w_e2)[tid];
        ((__half2*)(smc + E_W))[tid] = __floats2half2_rn(v.x, v.y);
    }
    // zero D (32*68 = 2176 floats)
    for (int k = tid; k < 2176; k += 256) Dsm[k] = 0.f;

#define ELOAD(ch, st) do { \
    { \
        int _row = tid >> 3, _q = tid & 7;   /* A: 32 rows x 8 chunks */ \
        uint32_t _sw = (uint32_t)(_row * 128 + ((_q ^ (_row & 7)) << 4)); \
        CP16(sb + E_A + (uint32_t)((st) * 4096) + _sw, \
             g_aH + (size_t)(mi + _row) * HDd + (ch) * 64 + _q * 8); \
    } \
    _Pragma("unroll") \
    for (int _rep = 0; _rep < 2; _rep++) {   /* C: 64 rows x 8 chunks */ \
        int _idx = tid + _rep * 256; \
        int _row = _idx >> 3, _q = _idx & 7; \
        uint32_t _sw = (uint32_t)(_row * 128 + ((_q ^ (_row & 7)) << 4)); \
        CP16(sb + E_C + (uint32_t)((st) * 8192) + _sw, \
             g_cH + (size_t)(mj + _row) * HDd + (ch) * 64 + _q * 8); \
    } } while (0)

    ELOAD(0, 0);
    CP_COMMIT();
    __syncthreads();

    const int jA = jb + g, jB = jA + 8;

    for (int ch = 0; ch < 8; ch++) {
        if (ch + 1 < 8) {
            ELOAD(ch + 1, (ch + 1) & 1);
            CP_COMMIT();
            asm volatile("cp.async.wait_group 1;" ::: "memory");
        } else {
            asm volatile("cp.async.wait_group 0;" ::: "memory");
        }
        __syncthreads();

        const uint32_t Ab = sb + E_A + (uint32_t)((ch & 1) * 4096);
        const uint32_t Cb = sb + E_C + (uint32_t)((ch & 1) * 8192);

        // c fragments (4 k16-frags) and w fragments for this chunk
        uint32_t cc[4][4], wf[4][2];
#pragma unroll
        for (int f = 0; f < 4; f++) {
            LDS32(cc[f][0], Cb + (uint32_t)(jA * 128 + (((2 * f)     ^ (jA & 7)) << 4) + 4 * t));
            LDS32(cc[f][1], Cb + (uint32_t)(jB * 128 + (((2 * f)     ^ (jB & 7)) << 4) + 4 * t));
            LDS32(cc[f][2], Cb + (uint32_t)(jA * 128 + (((2 * f + 1) ^ (jA & 7)) << 4) + 4 * t));
            LDS32(cc[f][3], Cb + (uint32_t)(jB * 128 + (((2 * f + 1) ^ (jB & 7)) << 4) + 4 * t));
            LDS32(wf[f][0], sb + E_W + (uint32_t)(ch * 128 + 32 * f + 4 * t));
            LDS32(wf[f][1], sb + E_W + (uint32_t)(ch * 128 + 32 * f + 4 * t + 16));
        }

#pragma unroll 4
        for (int ii = 0; ii < 16; ii += 2) {
            const int iX = i0w + ii;
            const int iY = iX + 1;
            uint32_t aAx[4], aBx[4], aAy[4], aBy[4];
#pragma unroll
            for (int f = 0; f < 4; f++) {
                LDS32(aAx[f], Ab + (uint32_t)(iX * 128 + (((2 * f)     ^ (iX & 7)) << 4) + 4 * t));
                LDS32(aBx[f], Ab + (uint32_t)(iX * 128 + (((2 * f + 1) ^ (iX & 7)) << 4) + 4 * t));
                LDS32(aAy[f], Ab + (uint32_t)(iY * 128 + (((2 * f)     ^ (iY & 7)) << 4) + 4 * t));
                LDS32(aBy[f], Ab + (uint32_t)(iY * 128 + (((2 * f + 1) ^ (iY & 7)) << 4) + 4 * t));
            }
            float D0[4] = {0.f, 0.f, 0.f, 0.f};
            float D1[4] = {0.f, 0.f, 0.f, 0.f};
#pragma unroll
            for (int f = 0; f < 4; f++) {
                uint32_t p0, p1, p2, p3, q0, q1, q2, q3;
                PRELU(p0, cc[f][0], aAx[f]);
                PRELU(p1, cc[f][1], aAx[f]);
                PRELU(p2, cc[f][2], aBx[f]);
                PRELU(p3, cc[f][3], aBx[f]);
                PRELU(q0, cc[f][0], aAy[f]);
                PRELU(q1, cc[f][1], aAy[f]);
                PRELU(q2, cc[f][2], aBy[f]);
                PRELU(q3, cc[f][3], aBy[f]);
                MMA16816(D0, p0, p1, p2, p3, wf[f][0], wf[f][1]);
                MMA16816(D1, q0, q1, q2, q3, wf[f][0], wf[f][1]);
            }
            if (t == 0) {                       // lanes holding D col 0
                float* dp0 = Dsm + iX * 68 + jb + g;
                float* dp1 = Dsm + iY * 68 + jb + g;
                dp0[0] += D0[0];                // row g
                dp0[8] += D0[2];                // row g+8
                dp1[0] += D1[0];
                dp1[8] += D1[2];
            }
        }
        __syncthreads();
    }

    const float be = b_e2[0];
#pragma unroll
    for (int k = 0; k < 8; k++) {
        int gi = k * 256 + tid;                 // 2048 = 32i x 64j
        int i = gi >> 6, j = gi & 63;
        out_end[(size_t)(bz * Nn + i0 + i) * Nn + j0 + j] = Dsm[i * 68 + j] + be;
    }
}

// -------- host --------
extern "C" void kernel_launch(void* const* d_in, const int* in_sizes, int n_in,
                              void* d_out, int out_size)
{
    (void)in_sizes; (void)n_in; (void)out_size;
    const float* emb  = (const float*)d_in[0];
    const float* W_s1 = (const float*)d_in[1];
    const float* b_s1 = (const float*)d_in[2];
    const float* w_s2 = (const float*)d_in[3];
    const float* b_s2 = (const float*)d_in[4];
    const float* W_e1 = (const float*)d_in[5];
    const float* b_e1 = (const float*)d_in[6];
    const float* w_e2 = (const float*)d_in[7];
    const float* b_e2 = (const float*)d_in[8];
    float* out = (float*)d_out;

    static bool attr_done = false;
    if (!attr_done) {
        cudaFuncSetAttribute(gemm_kernel, cudaFuncAttributeMaxDynamicSharedMemorySize, GEMM_SMEM);
        cudaFuncSetAttribute(end2_kernel, cudaFuncAttributeMaxDynamicSharedMemorySize, END_SMEM);
        attr_done = true;
    }

    prep_kernel<<<1024, 256>>>(emb, W_s1, W_e1, b_s2, out);

    dim3 gg(NTOT / BN, Mm / BM);                  // 24 x 8 = 192 CTAs
    gemm_kernel<<<gg, 256, GEMM_SMEM>>>(b_s1, w_s2, b_e1, out);

    dim3 ge(Nn / 64, Nn / 32, Bb);                // 8 x 16 x 2 = 256 CTAs
    end2_kernel<<<ge, 256, END_SMEM>>>(w_e2, b_e2, out + Mm);
}